// round 3
// baseline (speedup 1.0000x reference)
#include <cuda_runtime.h>

#define SEQ   4096
#define BATCH 4096
#define NIN   2
#define HID   8
#define CTAS  128
#define BPC   (BATCH / CTAS)   // 32 batches per CTA
#define TPB   (BPC * HID)      // 256 threads

__device__ __forceinline__ float ex2f_(float x) {
    float y; asm("ex2.approx.f32 %0, %1;" : "=f"(y) : "f"(x)); return y;
}
__device__ __forceinline__ float rcpf_(float x) {
    float y; asm("rcp.approx.f32 %0, %1;" : "=f"(y) : "f"(x)); return y;
}

// Packed fp32x2 ops (Blackwell)
__device__ __forceinline__ float2 ffma2(float2 a, float2 b, float2 c) {
    float2 d;
    asm("{\n\t"
        ".reg .b64 ra, rb, rc, rd;\n\t"
        "mov.b64 ra, {%2, %3};\n\t"
        "mov.b64 rb, {%4, %5};\n\t"
        "mov.b64 rc, {%6, %7};\n\t"
        "fma.rn.f32x2 rd, ra, rb, rc;\n\t"
        "mov.b64 {%0, %1}, rd;\n\t"
        "}"
        : "=f"(d.x), "=f"(d.y)
        : "f"(a.x), "f"(a.y), "f"(b.x), "f"(b.y), "f"(c.x), "f"(c.y));
    return d;
}
__device__ __forceinline__ float2 fmul2(float2 a, float2 b) {
    float2 d;
    asm("{\n\t"
        ".reg .b64 ra, rb, rd;\n\t"
        "mov.b64 ra, {%2, %3};\n\t"
        "mov.b64 rb, {%4, %5};\n\t"
        "mul.rn.f32x2 rd, ra, rb;\n\t"
        "mov.b64 {%0, %1}, rd;\n\t"
        "}"
        : "=f"(d.x), "=f"(d.y)
        : "f"(a.x), "f"(a.y), "f"(b.x), "f"(b.y));
    return d;
}
__device__ __forceinline__ float2 fadd2(float2 a, float2 b) {
    float2 d;
    asm("{\n\t"
        ".reg .b64 ra, rb, rd;\n\t"
        "mov.b64 ra, {%2, %3};\n\t"
        "mov.b64 rb, {%4, %5};\n\t"
        "add.rn.f32x2 rd, ra, rb;\n\t"
        "mov.b64 {%0, %1}, rd;\n\t"
        "}"
        : "=f"(d.x), "=f"(d.y)
        : "f"(a.x), "f"(a.y), "f"(b.x), "f"(b.y));
    return d;
}

__global__ void __launch_bounds__(TPB) lstm_kernel(
    const float* __restrict__ x,
    const float* __restrict__ h0,
    const float* __restrict__ c0,
    const float* __restrict__ W_ih,
    const float* __restrict__ W_hh,
    const float* __restrict__ b_ih,
    const float* __restrict__ b_hh,
    float* __restrict__ out)
{
    const int tid = threadIdx.x;
    const int g   = tid >> 3;   // batch group within CTA
    const int j   = tid & 7;    // h index within batch
    const int b   = blockIdx.x * BPC + g;

    const float LOG2E = 1.4426950408889634f;
    // Gate rows owned by this lane (PyTorch order i,f,g,o)
    const int ri = j, rf = 8 + j, rg = 16 + j, ro = 24 + j;
    // Fold activation argument scaling into the weights:
    //   sigmoid(u) = rcp(1 + exp2(-u*log2e))        -> rows i,f,o scaled by -log2e
    //   tanh(u)    = 2*rcp(1 + exp2(-2u*log2e)) - 1 -> row g scaled by -2*log2e
    const float si = -LOG2E, sf = -LOG2E, sg = -2.0f * LOG2E, so = -LOG2E;

    // Pair-packed weights: (i,f) pair and (g,o) pair
    float2 wif_h[HID], wgo_h[HID];
    #pragma unroll
    for (int k = 0; k < HID; k++) {
        wif_h[k] = make_float2(si * W_hh[ri * HID + k], sf * W_hh[rf * HID + k]);
        wgo_h[k] = make_float2(sg * W_hh[rg * HID + k], so * W_hh[ro * HID + k]);
    }
    const float2 wif_x0 = make_float2(si * W_ih[ri * NIN + 0], sf * W_ih[rf * NIN + 0]);
    const float2 wif_x1 = make_float2(si * W_ih[ri * NIN + 1], sf * W_ih[rf * NIN + 1]);
    const float2 wgo_x0 = make_float2(sg * W_ih[rg * NIN + 0], so * W_ih[ro * NIN + 0]);
    const float2 wgo_x1 = make_float2(sg * W_ih[rg * NIN + 1], so * W_ih[ro * NIN + 1]);
    const float2 bif = make_float2(si * (b_ih[ri] + b_hh[ri]), sf * (b_ih[rf] + b_hh[rf]));
    const float2 bgo = make_float2(sg * (b_ih[rg] + b_hh[rg]), so * (b_ih[ro] + b_hh[ro]));

    float c = c0[b * HID + j];
    float h = h0[b * HID + j];

    const size_t xstride = (size_t)BATCH * NIN;
    const float* xbase = x + (size_t)b * NIN;
    auto ldx = [&](int s) -> float2 {
        int sc = s < SEQ ? s : (SEQ - 1);
        return *(const float2*)(xbase + (size_t)sc * xstride);
    };

    // x-projection (bias + W_ih*x) for the CURRENT step, precomputed off the
    // recurrence chain. xpif/xpgo hold it for step s; each step computes the
    // next step's projection during the shfl-latency window.
    auto xproj = [&](float2 xv, float2& pif, float2& pgo) {
        float2 x0d = make_float2(xv.x, xv.x);
        float2 x1d = make_float2(xv.y, xv.y);
        pif = ffma2(wif_x1, x1d, ffma2(wif_x0, x0d, bif));
        pgo = ffma2(wgo_x1, x1d, ffma2(wgo_x0, x0d, bgo));
    };

    // Prefetch x: xa..xd hold x[s+1..s+4] at loop top for base step s.
    float2 xa = ldx(1), xb = ldx(2), xc = ldx(3), xd = ldx(4);
    float2 xpif, xpgo;
    xproj(ldx(0), xpif, xpgo);

    const unsigned FULL = 0xffffffffu;

    // One recurrence step. xnext = x[s+1]; consumes xpart(s), produces xpart(s+1).
    auto dostep = [&](float2 xnext) {
        // 8-lane group broadcast of h via width-8 shfl (no barrier, no smem)
        float e0 = __shfl_sync(FULL, h, 0, 8);
        float e1 = __shfl_sync(FULL, h, 1, 8);
        float e2 = __shfl_sync(FULL, h, 2, 8);
        float e3 = __shfl_sync(FULL, h, 3, 8);
        float e4 = __shfl_sync(FULL, h, 4, 8);
        float e5 = __shfl_sync(FULL, h, 5, 8);
        float e6 = __shfl_sync(FULL, h, 6, 8);
        float e7 = __shfl_sync(FULL, h, 7, 8);

        // Overlap shfl latency: next step's x projection (independent of h)
        float2 nxif, nxgo;
        xproj(xnext, nxif, nxgo);

        float2 d0 = make_float2(e0, e0), d1 = make_float2(e1, e1);
        float2 d2 = make_float2(e2, e2), d3 = make_float2(e3, e3);
        float2 d4 = make_float2(e4, e4), d5 = make_float2(e5, e5);
        float2 d6 = make_float2(e6, e6), d7 = make_float2(e7, e7);

        // Two balanced accumulation trees per gate-pair (depth ~5 ops)
        float2 aA = ffma2(wif_h[0], d0, xpif);
        float2 gA = ffma2(wgo_h[0], d0, xpgo);
        float2 aB = fmul2(wif_h[1], d1);
        float2 gB = fmul2(wgo_h[1], d1);
        aA = ffma2(wif_h[2], d2, aA);  gA = ffma2(wgo_h[2], d2, gA);
        aB = ffma2(wif_h[3], d3, aB);  gB = ffma2(wgo_h[3], d3, gB);
        aA = ffma2(wif_h[4], d4, aA);  gA = ffma2(wgo_h[4], d4, gA);
        aB = ffma2(wif_h[5], d5, aB);  gB = ffma2(wgo_h[5], d5, gB);
        aA = ffma2(wif_h[6], d6, aA);  gA = ffma2(wgo_h[6], d6, gA);
        aB = ffma2(wif_h[7], d7, aB);  gB = ffma2(wgo_h[7], d7, gB);
        float2 aif = fadd2(aA, aB);
        float2 ago = fadd2(gA, gB);

        // Activations (scales pre-folded into weights)
        float s_i = rcpf_(1.0f + ex2f_(aif.x));
        float s_f = rcpf_(1.0f + ex2f_(aif.y));
        float r_g = rcpf_(1.0f + ex2f_(ago.x));   // tanh(g) = 2*r_g - 1
        float s_o = rcpf_(1.0f + ex2f_(ago.y));

        float twoI = s_i + s_i;
        float twoO = s_o + s_o;
        // c = f*c + i*(2*r_g - 1)
        c = fmaf(s_f, c, fmaf(twoI, r_g, -s_i));
        // h = o * tanh(c) = 2*o*r_c - o
        float r_c = rcpf_(1.0f + ex2f_(c * (-2.0f * LOG2E)));
        h = fmaf(twoO, r_c, -s_o);

        xpif = nxif; xpgo = nxgo;
    };

    #pragma unroll 1
    for (int s = 0; s < SEQ; s += 4) {
        dostep(xa);  xa = ldx(s + 5);
        dostep(xb);  xb = ldx(s + 6);
        dostep(xc);  xc = ldx(s + 7);
        dostep(xd);  xd = ldx(s + 8);
    }

    out[b * HID + j] = h;
}

extern "C" void kernel_launch(void* const* d_in, const int* in_sizes, int n_in,
                              void* d_out, int out_size) {
    const float* x    = (const float*)d_in[0];
    const float* h0   = (const float*)d_in[1];
    const float* c0   = (const float*)d_in[2];
    const float* W_ih = (const float*)d_in[3];
    const float* W_hh = (const float*)d_in[4];
    const float* b_ih = (const float*)d_in[5];
    const float* b_hh = (const float*)d_in[6];
    lstm_kernel<<<CTAS, TPB>>>(x, h0, c0, W_ih, W_hh, b_ih, b_hh, (float*)d_out);
}

// round 6
// speedup vs baseline: 1.1138x; 1.1138x over previous
#include <cuda_runtime.h>

#define SEQ   4096
#define BATCH 4096
#define NIN   2
#define HID   8
#define CTAS  128
#define BPC   (BATCH / CTAS)   // 32 batches per CTA
#define TPB   (BPC * HID)      // 256 threads

typedef unsigned long long u64;

__device__ __forceinline__ float ex2f_(float x) {
    float y; asm("ex2.approx.f32 %0, %1;" : "=f"(y) : "f"(x)); return y;
}
__device__ __forceinline__ float rcpf_(float x) {
    float y; asm("rcp.approx.f32 %0, %1;" : "=f"(y) : "f"(x)); return y;
}

// Pack two floats into a b64 register pair (single MOV.64 in SASS).
__device__ __forceinline__ u64 pk2(float lo, float hi) {
    u64 d;
    asm("mov.b64 %0, {%1, %2};" : "=l"(d)
        : "r"(__float_as_uint(lo)), "r"(__float_as_uint(hi)));
    return d;
}
__device__ __forceinline__ void upk2(u64 v, float& lo, float& hi) {
    unsigned a, b;
    asm("mov.b64 {%0, %1}, %2;" : "=r"(a), "=r"(b) : "l"(v));
    lo = __uint_as_float(a); hi = __uint_as_float(b);
}

// Packed fp32x2 ops on b64 carriers — single SASS instruction each, no
// pack/unpack MOVs on the dependency chain.
__device__ __forceinline__ u64 ffma2(u64 a, u64 b, u64 c) {
    u64 d; asm("fma.rn.f32x2 %0, %1, %2, %3;" : "=l"(d) : "l"(a), "l"(b), "l"(c)); return d;
}
__device__ __forceinline__ u64 fmul2(u64 a, u64 b) {
    u64 d; asm("mul.rn.f32x2 %0, %1, %2;" : "=l"(d) : "l"(a), "l"(b)); return d;
}
__device__ __forceinline__ u64 fadd2(u64 a, u64 b) {
    u64 d; asm("add.rn.f32x2 %0, %1, %2;" : "=l"(d) : "l"(a), "l"(b)); return d;
}

__global__ void __launch_bounds__(TPB) lstm_kernel(
    const float* __restrict__ x,
    const float* __restrict__ h0,
    const float* __restrict__ c0,
    const float* __restrict__ W_ih,
    const float* __restrict__ W_hh,
    const float* __restrict__ b_ih,
    const float* __restrict__ b_hh,
    float* __restrict__ out)
{
    const int tid = threadIdx.x;
    const int g   = tid >> 3;   // batch group within CTA
    const int j   = tid & 7;    // h index within batch
    const int b   = blockIdx.x * BPC + g;

    const float LOG2E = 1.4426950408889634f;
    // Gate rows owned by this lane (PyTorch order i,f,g,o)
    const int ri = j, rf = 8 + j, rg = 16 + j, ro = 24 + j;
    // Fold activation argument scaling into the weights:
    //   sigmoid(u) = rcp(1 + exp2(-u*log2e))        -> rows i,f,o scaled by -log2e
    //   tanh(u)    = 2*rcp(1 + exp2(-2u*log2e)) - 1 -> row g scaled by -2*log2e
    const float si = -LOG2E, sf = -LOG2E, sg = -2.0f * LOG2E, so = -LOG2E;

    // Pair-packed weights as b64 carriers: (i,f) pair and (g,o) pair
    u64 wif_h[HID], wgo_h[HID];
    #pragma unroll
    for (int k = 0; k < HID; k++) {
        wif_h[k] = pk2(si * W_hh[ri * HID + k], sf * W_hh[rf * HID + k]);
        wgo_h[k] = pk2(sg * W_hh[rg * HID + k], so * W_hh[ro * HID + k]);
    }
    const u64 wif_x0 = pk2(si * W_ih[ri * NIN + 0], sf * W_ih[rf * NIN + 0]);
    const u64 wif_x1 = pk2(si * W_ih[ri * NIN + 1], sf * W_ih[rf * NIN + 1]);
    const u64 wgo_x0 = pk2(sg * W_ih[rg * NIN + 0], so * W_ih[ro * NIN + 0]);
    const u64 wgo_x1 = pk2(sg * W_ih[rg * NIN + 1], so * W_ih[ro * NIN + 1]);
    const u64 bif = pk2(si * (b_ih[ri] + b_hh[ri]), sf * (b_ih[rf] + b_hh[rf]));
    const u64 bgo = pk2(sg * (b_ih[rg] + b_hh[rg]), so * (b_ih[ro] + b_hh[ro]));

    // h exchange: duplicated (h,h) pairs as u64 so LDS.128 yields two ready
    // f32x2 multiplicands. Double-buffered; consumers are in the same warp.
    __shared__ __align__(16) u64 sh[2][BPC][HID];

    float c = c0[b * HID + j];
    float h = h0[b * HID + j];
    sh[0][g][j] = pk2(h, h);
    __syncwarp();

    const size_t xstride = (size_t)BATCH * NIN;
    const float* xbase = x + (size_t)b * NIN;
    auto ldx = [&](int s) -> float2 {
        int sc = s < SEQ ? s : (SEQ - 1);
        return *(const float2*)(xbase + (size_t)sc * xstride);
    };

    // x-projection (bias + W_ih*x) computed off the recurrence chain.
    auto xproj = [&](float2 xv, u64& pif, u64& pgo) {
        u64 x0d = pk2(xv.x, xv.x);
        u64 x1d = pk2(xv.y, xv.y);
        pif = ffma2(wif_x1, x1d, ffma2(wif_x0, x0d, bif));
        pgo = ffma2(wgo_x1, x1d, ffma2(wgo_x0, x0d, bgo));
    };

    float2 xa = ldx(1), xb = ldx(2), xc = ldx(3), xd = ldx(4);
    u64 xpif, xpgo;
    xproj(ldx(0), xpif, xpgo);

    auto dostep = [&](float2 xnext, int rd) {
        // 4x LDS.128: eight duplicated h pairs for this batch group
        const ulonglong2* hp = (const ulonglong2*)&sh[rd][g][0];
        ulonglong2 p0 = hp[0], p1 = hp[1], p2 = hp[2], p3 = hp[3];

        // Fill the LDS latency window with next step's x projection
        u64 nxif, nxgo;
        xproj(xnext, nxif, nxgo);

        // Two balanced accumulation trees per gate-pair (pure FFMA2 chain)
        u64 aA = ffma2(wif_h[0], p0.x, xpif);
        u64 gA = ffma2(wgo_h[0], p0.x, xpgo);
        u64 aB = fmul2(wif_h[1], p0.y);
        u64 gB = fmul2(wgo_h[1], p0.y);
        aA = ffma2(wif_h[2], p1.x, aA);  gA = ffma2(wgo_h[2], p1.x, gA);
        aB = ffma2(wif_h[3], p1.y, aB);  gB = ffma2(wgo_h[3], p1.y, gB);
        aA = ffma2(wif_h[4], p2.x, aA);  gA = ffma2(wgo_h[4], p2.x, gA);
        aB = ffma2(wif_h[5], p2.y, aB);  gB = ffma2(wgo_h[5], p2.y, gB);
        aA = ffma2(wif_h[6], p3.x, aA);  gA = ffma2(wgo_h[6], p3.x, gA);
        aB = ffma2(wif_h[7], p3.y, aB);  gB = ffma2(wgo_h[7], p3.y, gB);
        u64 aif = fadd2(aA, aB);
        u64 ago = fadd2(gA, gB);

        float a_i, a_f, a_g, a_o;
        upk2(aif, a_i, a_f);
        upk2(ago, a_g, a_o);

        // Activations (argument scales pre-folded into weights)
        float s_i = rcpf_(1.0f + ex2f_(a_i));
        float s_f = rcpf_(1.0f + ex2f_(a_f));
        float r_g = rcpf_(1.0f + ex2f_(a_g));   // tanh(g) = 2*r_g - 1
        float s_o = rcpf_(1.0f + ex2f_(a_o));

        float twoI = s_i + s_i;
        float twoO = s_o + s_o;
        // c = f*c + i*(2*r_g - 1)
        c = fmaf(s_f, c, fmaf(twoI, r_g, -s_i));
        // h = o*tanh(c) = 2*o*rcp(1+exp2(2c*log2e)) - o
        float r_c = rcpf_(1.0f + ex2f_(c * (-2.0f * LOG2E)));
        h = fmaf(twoO, r_c, -s_o);

        sh[rd ^ 1][g][j] = pk2(h, h);
        __syncwarp();

        xpif = nxif; xpgo = nxgo;
    };

    #pragma unroll 1
    for (int s = 0; s < SEQ; s += 4) {
        dostep(xa, 0);  xa = ldx(s + 5);
        dostep(xb, 1);  xb = ldx(s + 6);
        dostep(xc, 0);  xc = ldx(s + 7);
        dostep(xd, 1);  xd = ldx(s + 8);
    }

    out[b * HID + j] = h;
}

extern "C" void kernel_launch(void* const* d_in, const int* in_sizes, int n_in,
                              void* d_out, int out_size) {
    const float* x    = (const float*)d_in[0];
    const float* h0   = (const float*)d_in[1];
    const float* c0   = (const float*)d_in[2];
    const float* W_ih = (const float*)d_in[3];
    const float* W_hh = (const float*)d_in[4];
    const float* b_ih = (const float*)d_in[5];
    const float* b_hh = (const float*)d_in[6];
    lstm_kernel<<<CTAS, TPB>>>(x, h0, c0, W_ih, W_hh, b_ih, b_hh, (float*)d_out);
}

// round 7
// speedup vs baseline: 1.3324x; 1.1963x over previous
#include <cuda_runtime.h>

#define SEQ   4096
#define BATCH 4096
#define NIN   2
#define HID   8
#define CTAS  128
#define BPC   (BATCH / CTAS)   // 32 batches per CTA
#define TPB   (BPC * HID)      // 256 threads

typedef unsigned long long u64;

// MUFU.TANH: single-instruction tanh (sm_75+), max abs err ~2^-10.7
__device__ __forceinline__ float tanhap_(float x) {
    float y; asm("tanh.approx.f32 %0, %1;" : "=f"(y) : "f"(x)); return y;
}

// Pack two floats into a b64 register pair.
__device__ __forceinline__ u64 pk2(float lo, float hi) {
    u64 d;
    asm("mov.b64 %0, {%1, %2};" : "=l"(d)
        : "r"(__float_as_uint(lo)), "r"(__float_as_uint(hi)));
    return d;
}
__device__ __forceinline__ void upk2(u64 v, float& lo, float& hi) {
    unsigned a, b;
    asm("mov.b64 {%0, %1}, %2;" : "=r"(a), "=r"(b) : "l"(v));
    lo = __uint_as_float(a); hi = __uint_as_float(b);
}

// Packed fp32x2 ops on b64 carriers — single SASS instruction each.
__device__ __forceinline__ u64 ffma2(u64 a, u64 b, u64 c) {
    u64 d; asm("fma.rn.f32x2 %0, %1, %2, %3;" : "=l"(d) : "l"(a), "l"(b), "l"(c)); return d;
}
__device__ __forceinline__ u64 fmul2(u64 a, u64 b) {
    u64 d; asm("mul.rn.f32x2 %0, %1, %2;" : "=l"(d) : "l"(a), "l"(b)); return d;
}
__device__ __forceinline__ u64 fadd2(u64 a, u64 b) {
    u64 d; asm("add.rn.f32x2 %0, %1, %2;" : "=l"(d) : "l"(a), "l"(b)); return d;
}

__global__ void __launch_bounds__(TPB) lstm_kernel(
    const float* __restrict__ x,
    const float* __restrict__ h0,
    const float* __restrict__ c0,
    const float* __restrict__ W_ih,
    const float* __restrict__ W_hh,
    const float* __restrict__ b_ih,
    const float* __restrict__ b_hh,
    float* __restrict__ out)
{
    const int tid = threadIdx.x;
    const int g   = tid >> 3;   // batch group within CTA
    const int j   = tid & 7;    // h index within batch
    const int b   = blockIdx.x * BPC + g;

    // Gate rows owned by this lane (PyTorch order i,f,g,o)
    const int ri = j, rf = 8 + j, rg = 16 + j, ro = 24 + j;
    // Activation plan (all via single-instruction MUFU.TANH):
    //   sigmoid(u) = 0.5*tanh(u/2) + 0.5  -> fold the 1/2 into rows i,f,o
    //   tanh(u)                            -> row g unscaled
    const float si = 0.5f, sf = 0.5f, sg = 1.0f, so = 0.5f;

    // Pair-packed weights as b64 carriers: (i,f) pair and (g,o) pair
    u64 wif_h[HID], wgo_h[HID];
    #pragma unroll
    for (int k = 0; k < HID; k++) {
        wif_h[k] = pk2(si * W_hh[ri * HID + k], sf * W_hh[rf * HID + k]);
        wgo_h[k] = pk2(sg * W_hh[rg * HID + k], so * W_hh[ro * HID + k]);
    }
    const u64 wif_x0 = pk2(si * W_ih[ri * NIN + 0], sf * W_ih[rf * NIN + 0]);
    const u64 wif_x1 = pk2(si * W_ih[ri * NIN + 1], sf * W_ih[rf * NIN + 1]);
    const u64 wgo_x0 = pk2(sg * W_ih[rg * NIN + 0], so * W_ih[ro * NIN + 0]);
    const u64 wgo_x1 = pk2(sg * W_ih[rg * NIN + 1], so * W_ih[ro * NIN + 1]);
    const u64 bif = pk2(si * (b_ih[ri] + b_hh[ri]), sf * (b_ih[rf] + b_hh[rf]));
    const u64 bgo = pk2(sg * (b_ih[rg] + b_hh[rg]), so * (b_ih[ro] + b_hh[ro]));

    // h exchange: duplicated (h,h) pairs as u64 so LDS.128 yields two ready
    // f32x2 multiplicands. Double-buffered; consumers are in the same warp.
    __shared__ __align__(16) u64 sh[2][BPC][HID];

    float c = c0[b * HID + j];
    float h = h0[b * HID + j];
    sh[0][g][j] = pk2(h, h);
    __syncwarp();

    const size_t xstride = (size_t)BATCH * NIN;
    const float* xbase = x + (size_t)b * NIN;
    auto ldx = [&](int s) -> float2 {
        int sc = s < SEQ ? s : (SEQ - 1);
        return *(const float2*)(xbase + (size_t)sc * xstride);
    };

    // x-projection (bias + W_ih*x) computed off the recurrence chain.
    auto xproj = [&](float2 xv, u64& pif, u64& pgo) {
        u64 x0d = pk2(xv.x, xv.x);
        u64 x1d = pk2(xv.y, xv.y);
        pif = ffma2(wif_x1, x1d, ffma2(wif_x0, x0d, bif));
        pgo = ffma2(wgo_x1, x1d, ffma2(wgo_x0, x0d, bgo));
    };

    float2 xa = ldx(1), xb = ldx(2), xc = ldx(3), xd = ldx(4);
    u64 xpif, xpgo;
    xproj(ldx(0), xpif, xpgo);

    auto dostep = [&](float2 xnext, int rd) {
        // 4x LDS.128: eight duplicated h pairs for this batch group
        const ulonglong2* hp = (const ulonglong2*)&sh[rd][g][0];
        ulonglong2 p0 = hp[0], p1 = hp[1], p2 = hp[2], p3 = hp[3];

        // Fill the LDS latency window with next step's x projection
        u64 nxif, nxgo;
        xproj(xnext, nxif, nxgo);

        // Two balanced accumulation trees per gate-pair (pure FFMA2)
        u64 aA = ffma2(wif_h[0], p0.x, xpif);
        u64 gA = ffma2(wgo_h[0], p0.x, xpgo);
        u64 aB = fmul2(wif_h[1], p0.y);
        u64 gB = fmul2(wgo_h[1], p0.y);
        aA = ffma2(wif_h[2], p1.x, aA);  gA = ffma2(wgo_h[2], p1.x, gA);
        aB = ffma2(wif_h[3], p1.y, aB);  gB = ffma2(wgo_h[3], p1.y, gB);
        aA = ffma2(wif_h[4], p2.x, aA);  gA = ffma2(wgo_h[4], p2.x, gA);
        aB = ffma2(wif_h[5], p2.y, aB);  gB = ffma2(wgo_h[5], p2.y, gB);
        aA = ffma2(wif_h[6], p3.x, aA);  gA = ffma2(wgo_h[6], p3.x, gA);
        aB = ffma2(wif_h[7], p3.y, aB);  gB = ffma2(wgo_h[7], p3.y, gB);
        u64 aif = fadd2(aA, aB);
        u64 ago = fadd2(gA, gB);

        float a_i, a_f, a_g, a_o;
        upk2(aif, a_i, a_f);
        upk2(ago, a_g, a_o);

        // Activations: 5 MUFU.TANH total (was 10 MUFU as EX2+RCP pairs).
        float t_i = tanhap_(a_i);       // a_i already = u_i/2
        float t_f = tanhap_(a_f);
        float t_g = tanhap_(a_g);       // true tanh(g)
        float t_o = tanhap_(a_o);

        float s_i = fmaf(0.5f, t_i, 0.5f);
        float s_f = fmaf(0.5f, t_f, 0.5f);
        float s_o = fmaf(0.5f, t_o, 0.5f);

        // c = f*c + i*g
        c = fmaf(s_f, c, s_i * t_g);
        // h = o * tanh(c)
        h = s_o * tanhap_(c);

        sh[rd ^ 1][g][j] = pk2(h, h);
        __syncwarp();

        xpif = nxif; xpgo = nxgo;
    };

    #pragma unroll 1
    for (int s = 0; s < SEQ; s += 4) {
        dostep(xa, 0);  xa = ldx(s + 5);
        dostep(xb, 1);  xb = ldx(s + 6);
        dostep(xc, 0);  xc = ldx(s + 7);
        dostep(xd, 1);  xd = ldx(s + 8);
    }

    out[b * HID + j] = h;
}

extern "C" void kernel_launch(void* const* d_in, const int* in_sizes, int n_in,
                              void* d_out, int out_size) {
    const float* x    = (const float*)d_in[0];
    const float* h0   = (const float*)d_in[1];
    const float* c0   = (const float*)d_in[2];
    const float* W_ih = (const float*)d_in[3];
    const float* W_hh = (const float*)d_in[4];
    const float* b_ih = (const float*)d_in[5];
    const float* b_hh = (const float*)d_in[6];
    lstm_kernel<<<CTAS, TPB>>>(x, h0, c0, W_ih, W_hh, b_ih, b_hh, (float*)d_out);
}